// round 4
// baseline (speedup 1.0000x reference)
#include <cuda_runtime.h>

// Problem constants (capacities; runtime sizes derived from in_sizes)
#define MAXN 100000
#define MAXE 1600000
#define HD   256   // NUM_HEADS * OUT_FEATS
#define INF_ 128

// ---------------- scratch (device globals; no allocation allowed) ----------
__device__ float        g_ft[(size_t)MAXN * HD];     // 102.4 MB
__device__ float        g_el[MAXN * 8];
__device__ float        g_er[MAXN * 8];
__device__ float        g_e [(size_t)MAXE * 8];      // 51.2 MB (e, then exp in-place)
__device__ unsigned int g_emax[MAXN * 8];
__device__ float        g_esum[MAXN * 8];
__device__ int          g_deg[MAXN];
__device__ int          g_rowoff[MAXN + 1];
__device__ int          g_cursor[MAXN];
__device__ int          g_eids[MAXE];
__device__ int          g_bsum[1024];

// ---------------- init ------------------------------------------------------
__global__ void k_init(int n) {
    int i = blockIdx.x * blockDim.x + threadIdx.x;
    int n8 = n * 8;
    if (i < n8) { g_esum[i] = 0.f; g_emax[i] = 0xFF800000u; /* -inf bits */ }
    if (i < n)  g_deg[i] = 0;
}

// ---------------- GEMM: ft = feat @ W  (128-node tile, W resident, f32x2) ---
// block = 512 threads; tile = 128 nodes x 256 cols; thread = 4 nodes x 16 cols
__global__ __launch_bounds__(512, 1)
void k_gemm(const float* __restrict__ feat, const float* __restrict__ W, int n) {
    extern __shared__ float sm[];
    float* Ws = sm;                 // 128 x 256 = 32768 floats (128 KB)
    float* fs = sm + 32768;         // 128 x 129 (padded)      (66 KB)
    const int tid = threadIdx.x;
    const int n0  = blockIdx.x * 128;

    for (int i = tid; i < 8192; i += 512)
        ((float4*)Ws)[i] = ((const float4*)W)[i];
    for (int i = tid; i < 4096; i += 512) {
        int r = i >> 5, c4 = i & 31;
        float4 v = make_float4(0.f, 0.f, 0.f, 0.f);
        if (n0 + r < n) v = ((const float4*)feat)[(size_t)(n0 + r) * 32 + c4];
        float* d = fs + r * 129 + c4 * 4;
        d[0] = v.x; d[1] = v.y; d[2] = v.z; d[3] = v.w;
    }
    __syncthreads();

    const int cg = tid & 15;        // 16-col group
    const int ng = tid >> 4;        // 4-node group (0..31)
    unsigned long long acc[32];
#pragma unroll
    for (int i = 0; i < 32; i++) acc[i] = 0ULL;

    const float* f0 = fs + ng * 4 * 129;
    const float* wc = Ws + cg * 16;

#pragma unroll 2
    for (int k = 0; k < 128; k++) {
        unsigned long long a[4];
#pragma unroll
        for (int i = 0; i < 4; i++) {
            unsigned int fb = __float_as_uint(f0[i * 129 + k]);
            asm("mov.b64 %0, {%1, %1};" : "=l"(a[i]) : "r"(fb));
        }
        const ulonglong2* wp = reinterpret_cast<const ulonglong2*>(wc + (size_t)k * HD);
        ulonglong2 w0 = wp[0], w1 = wp[1], w2 = wp[2], w3 = wp[3];
        unsigned long long w[8] = {w0.x, w0.y, w1.x, w1.y, w2.x, w2.y, w3.x, w3.y};
#pragma unroll
        for (int i = 0; i < 4; i++)
#pragma unroll
            for (int j = 0; j < 8; j++)
                asm("fma.rn.f32x2 %0, %1, %2, %0;" : "+l"(acc[i * 8 + j]) : "l"(a[i]), "l"(w[j]));
    }

#pragma unroll
    for (int i = 0; i < 4; i++) {
        int node = n0 + ng * 4 + i;
        if (node < n) {
            float* o = g_ft + (size_t)node * HD + cg * 16;
#pragma unroll
            for (int j = 0; j < 8; j++) {
                unsigned int lo, hi;
                asm("mov.b64 {%0, %1}, %2;" : "=r"(lo), "=r"(hi) : "l"(acc[i * 8 + j]));
                o[2 * j]     = __uint_as_float(lo);
                o[2 * j + 1] = __uint_as_float(hi);
            }
        }
    }
}

// ---------------- el / er (warp per node) -----------------------------------
__global__ void k_elr(const float* __restrict__ al, const float* __restrict__ ar, int n) {
    int warp = (blockIdx.x * blockDim.x + threadIdx.x) >> 5;
    int lane = threadIdx.x & 31;
    if (warp >= n) return;
    const float* f = g_ft + (size_t)warp * HD;
#pragma unroll
    for (int h = 0; h < 8; h++) {
        float v  = f[h * 32 + lane];
        float s1 = v * al[h * 32 + lane];
        float s2 = v * ar[h * 32 + lane];
#pragma unroll
        for (int o = 16; o; o >>= 1) {
            s1 += __shfl_xor_sync(0xffffffffu, s1, o);
            s2 += __shfl_xor_sync(0xffffffffu, s2, o);
        }
        if (lane == 0) { g_el[warp * 8 + h] = s1; g_er[warp * 8 + h] = s2; }
    }
}

// ---------------- CSR build --------------------------------------------------
__global__ void k_hist(const int* __restrict__ dst, int e) {
    int i = blockIdx.x * blockDim.x + threadIdx.x;
    if (i < e) atomicAdd(&g_deg[dst[i]], 1);
}

__global__ void k_scan1(int n) {
    __shared__ int sm[1024];
    int i = blockIdx.x * 1024 + threadIdx.x;
    int v = (i < n) ? g_deg[i] : 0;
    sm[threadIdx.x] = v;
    __syncthreads();
    for (int off = 1; off < 1024; off <<= 1) {
        int t = (threadIdx.x >= off) ? sm[threadIdx.x - off] : 0;
        __syncthreads();
        sm[threadIdx.x] += t;
        __syncthreads();
    }
    if (i < n) g_rowoff[i] = sm[threadIdx.x] - v;   // exclusive within block
    if (threadIdx.x == 1023) g_bsum[blockIdx.x] = sm[1023];
}

__global__ void k_scan2(int nb) {
    if (threadIdx.x == 0 && blockIdx.x == 0) {
        int s = 0;
        for (int b = 0; b < nb; b++) { int t = g_bsum[b]; g_bsum[b] = s; s += t; }
    }
}

__global__ void k_scan3(int n, int e) {
    int i = blockIdx.x * 1024 + threadIdx.x;
    if (i < n) {
        int r = g_rowoff[i] + g_bsum[i >> 10];
        g_rowoff[i] = r;
        g_cursor[i] = r;
    }
    if (i == 0) g_rowoff[n] = e;
}

__global__ void k_scatter(const int* __restrict__ dst, int e) {
    int i = blockIdx.x * blockDim.x + threadIdx.x;
    if (i < e) {
        int p = atomicAdd(&g_cursor[dst[i]], 1);
        g_eids[p] = i;
    }
}

// ---------------- edge pass 1: e = leakyrelu(el[src]+er[dst]); segment max ---
__global__ void k_edge1(const int* __restrict__ src, const int* __restrict__ dst, int e) {
    int i = blockIdx.x * blockDim.x + threadIdx.x;
    if (i >= e) return;
    int s = src[i], d = dst[i];
    const float4* lp = (const float4*)(g_el + (size_t)s * 8);
    const float4* rp = (const float4*)(g_er + (size_t)d * 8);
    float4 l0 = lp[0], l1 = lp[1], r0 = rp[0], r1 = rp[1];
    float ev[8] = {l0.x + r0.x, l0.y + r0.y, l0.z + r0.z, l0.w + r0.w,
                   l1.x + r1.x, l1.y + r1.y, l1.z + r1.z, l1.w + r1.w};
#pragma unroll
    for (int h = 0; h < 8; h++) ev[h] = ev[h] > 0.f ? ev[h] : 0.2f * ev[h];
    float4* ep = (float4*)(g_e + (size_t)i * 8);
    ep[0] = make_float4(ev[0], ev[1], ev[2], ev[3]);
    ep[1] = make_float4(ev[4], ev[5], ev[6], ev[7]);
    unsigned int* mp = g_emax + (size_t)d * 8;
#pragma unroll
    for (int h = 0; h < 8; h++) {
        float v = ev[h];
        if (v >= 0.f) atomicMax((int*)(mp + h), __float_as_int(v));
        else          atomicMin(mp + h, __float_as_uint(v));
    }
}

// ---------------- edge pass 2: exp(e - max) in-place; segment sum ------------
__global__ void k_edge2(const int* __restrict__ dst, int e) {
    int i = blockIdx.x * blockDim.x + threadIdx.x;
    if (i >= e) return;
    int d = dst[i];
    float4* ep = (float4*)(g_e + (size_t)i * 8);
    float4 x0 = ep[0], x1 = ep[1];
    const float4* mp = (const float4*)(g_emax + (size_t)d * 8);
    float4 m0 = mp[0], m1 = mp[1];
    float ex[8];
    ex[0] = __expf(x0.x - m0.x); ex[1] = __expf(x0.y - m0.y);
    ex[2] = __expf(x0.z - m0.z); ex[3] = __expf(x0.w - m0.w);
    ex[4] = __expf(x1.x - m1.x); ex[5] = __expf(x1.y - m1.y);
    ex[6] = __expf(x1.z - m1.z); ex[7] = __expf(x1.w - m1.w);
    ep[0] = make_float4(ex[0], ex[1], ex[2], ex[3]);
    ep[1] = make_float4(ex[4], ex[5], ex[6], ex[7]);
    float* sp = g_esum + (size_t)d * 8;
#pragma unroll
    for (int h = 0; h < 8; h++) atomicAdd(sp + h, ex[h]);
}

// ---------------- aggregate: warp per node, no atomics -----------------------
__global__ void k_agg(const int* __restrict__ src, const float* __restrict__ bias,
                      float* __restrict__ out_h, float* __restrict__ out_attn, int n) {
    int warp = (blockIdx.x * blockDim.x + threadIdx.x) >> 5;
    int lane = threadIdx.x & 31;
    if (warp >= n) return;
    int beg = g_rowoff[warp], end = g_rowoff[warp + 1];

    float invs = 0.f;
    if (lane < 8) {
        float s = g_esum[warp * 8 + lane];
        invs = (s > 0.f) ? 1.f / s : 0.f;
    }

    float acc[8];
#pragma unroll
    for (int h = 0; h < 8; h++) acc[h] = 0.f;

    for (int p = beg; p < end; p++) {
        int e = g_eids[p];
        int s = src[e];
        float a8 = 0.f;
        if (lane < 8) {
            a8 = g_e[(size_t)e * 8 + lane] * invs;   // a[e,h]
            out_attn[(size_t)e * 8 + lane] = a8;
        }
        const float* fp = g_ft + (size_t)s * HD + lane;
#pragma unroll
        for (int h = 0; h < 8; h++) {
            float a = __shfl_sync(0xffffffffu, a8, h);
            acc[h] += a * fp[h * 32];
        }
    }

    float msum = 0.f;
#pragma unroll
    for (int h = 0; h < 8; h++) msum += acc[h] + bias[h * 32 + lane];
    out_h[(size_t)warp * 32 + lane] = msum * 0.125f;
}

// ---------------- launch ------------------------------------------------------
extern "C" void kernel_launch(void* const* d_in, const int* in_sizes, int n_in,
                              void* d_out, int out_size) {
    const float* feat = (const float*)d_in[0];
    const int*   src  = (const int*)d_in[1];
    const int*   dst  = (const int*)d_in[2];
    const float* W    = (const float*)d_in[3];
    const float* al   = (const float*)d_in[4];
    const float* ar   = (const float*)d_in[5];
    const float* bias = (const float*)d_in[6];

    int n = in_sizes[0] / INF_;
    int e = in_sizes[1];

    float* out      = (float*)d_out;
    float* out_h    = out;                       // [n, 32]
    float* out_attn = out + (size_t)n * 32;      // [e, 8]

    const int SMEM = (32768 + 128 * 129) * 4;    // 197120 B
    cudaFuncSetAttribute(k_gemm, cudaFuncAttributeMaxDynamicSharedMemorySize, SMEM);

    k_init<<<(n * 8 + 255) / 256, 256>>>(n);
    k_gemm<<<(n + 127) / 128, 512, SMEM>>>(feat, W, n);
    k_elr<<<(n + 7) / 8, 256>>>(al, ar, n);

    int nb = (n + 1023) / 1024;
    k_hist<<<(e + 255) / 256, 256>>>(dst, e);
    k_scan1<<<nb, 1024>>>(n);
    k_scan2<<<1, 32>>>(nb);
    k_scan3<<<nb, 1024>>>(n, e);
    k_scatter<<<(e + 255) / 256, 256>>>(dst, e);

    k_edge1<<<(e + 255) / 256, 256>>>(src, dst, e);
    k_edge2<<<(e + 255) / 256, 256>>>(dst, e);
    k_agg<<<(n + 7) / 8, 256>>>(src, bias, out_h, out_attn, n);
}

// round 5
// speedup vs baseline: 1.0867x; 1.0867x over previous
#include <cuda_runtime.h>

#define MAXN 100000
#define MAXE 1600000
#define HD   256
#define INF_ 128

// ---------------- scratch ----------------------------------------------------
__device__ float g_ft[(size_t)MAXN * HD];     // 102.4 MB
__device__ float g_el[MAXN * 8];
__device__ float g_er[MAXN * 8];
__device__ int   g_deg[MAXN];
__device__ int   g_rowoff[MAXN + 1];
__device__ int   g_cursor[MAXN];
__device__ int   g_eids[MAXE];
__device__ int   g_bsum[1024];

// ---------------- init --------------------------------------------------------
__global__ void k_init(int n) {
    int i = blockIdx.x * blockDim.x + threadIdx.x;
    if (i < n) g_deg[i] = 0;
}

// ---------------- GEMM + fused el/er epilogue ---------------------------------
// block = 512 threads; tile = 128 nodes x 256 cols; thread = 4 nodes x 16 cols
__global__ __launch_bounds__(512, 1)
void k_gemm(const float* __restrict__ feat, const float* __restrict__ W,
            const float* __restrict__ al, const float* __restrict__ ar, int n) {
    extern __shared__ float sm[];
    float* Ws = sm;                 // 128 x 256 floats (128 KB)
    float* fs = sm + 32768;         // 128 x 129 padded (66 KB)
    const int tid = threadIdx.x;
    const int n0  = blockIdx.x * 128;

    for (int i = tid; i < 8192; i += 512)
        ((float4*)Ws)[i] = ((const float4*)W)[i];
    for (int i = tid; i < 4096; i += 512) {
        int r = i >> 5, c4 = i & 31;
        float4 v = make_float4(0.f, 0.f, 0.f, 0.f);
        if (n0 + r < n) v = ((const float4*)feat)[(size_t)(n0 + r) * 32 + c4];
        float* d = fs + r * 129 + c4 * 4;
        d[0] = v.x; d[1] = v.y; d[2] = v.z; d[3] = v.w;
    }
    __syncthreads();

    const int cg = tid & 15;        // 16-col group (all cols within head cg>>1)
    const int ng = tid >> 4;        // 4-node group
    unsigned long long acc[32];
#pragma unroll
    for (int i = 0; i < 32; i++) acc[i] = 0ULL;

    const float* f0 = fs + ng * 4 * 129;
    const float* wc = Ws + cg * 16;

#pragma unroll 2
    for (int k = 0; k < 128; k++) {
        unsigned long long a[4];
#pragma unroll
        for (int i = 0; i < 4; i++) {
            unsigned int fb = __float_as_uint(f0[i * 129 + k]);
            asm("mov.b64 %0, {%1, %1};" : "=l"(a[i]) : "r"(fb));
        }
        const ulonglong2* wp = reinterpret_cast<const ulonglong2*>(wc + (size_t)k * HD);
        ulonglong2 w0 = wp[0], w1 = wp[1], w2 = wp[2], w3 = wp[3];
        unsigned long long w[8] = {w0.x, w0.y, w1.x, w1.y, w2.x, w2.y, w3.x, w3.y};
#pragma unroll
        for (int i = 0; i < 4; i++)
#pragma unroll
            for (int j = 0; j < 8; j++)
                asm("fma.rn.f32x2 %0, %1, %2, %0;" : "+l"(acc[i * 8 + j]) : "l"(a[i]), "l"(w[j]));
    }

    // attn_l / attn_r slices for this thread's 16 columns
    float alv[16], arv[16];
#pragma unroll
    for (int j = 0; j < 16; j++) {
        alv[j] = __ldg(al + cg * 16 + j);
        arv[j] = __ldg(ar + cg * 16 + j);
    }

#pragma unroll
    for (int i = 0; i < 4; i++) {
        int node = n0 + ng * 4 + i;
        float pl = 0.f, pr = 0.f;
        float vals[16];
#pragma unroll
        for (int j = 0; j < 8; j++) {
            unsigned int lo, hi;
            asm("mov.b64 {%0, %1}, %2;" : "=r"(lo), "=r"(hi) : "l"(acc[i * 8 + j]));
            float flo = __uint_as_float(lo), fhi = __uint_as_float(hi);
            vals[2 * j] = flo; vals[2 * j + 1] = fhi;
            pl += flo * alv[2 * j] + fhi * alv[2 * j + 1];
            pr += flo * arv[2 * j] + fhi * arv[2 * j + 1];
        }
        // pair-reduce across the two 16-col halves of this head (lanes cg, cg^1)
        pl += __shfl_xor_sync(0xffffffffu, pl, 1);
        pr += __shfl_xor_sync(0xffffffffu, pr, 1);
        if (node < n) {
            float* o = g_ft + (size_t)node * HD + cg * 16;
#pragma unroll
            for (int j = 0; j < 16; j++) o[j] = vals[j];
            if ((cg & 1) == 0) {
                g_el[node * 8 + (cg >> 1)] = pl;
                g_er[node * 8 + (cg >> 1)] = pr;
            }
        }
    }
}

// ---------------- CSR build ----------------------------------------------------
__global__ void k_hist(const int* __restrict__ dst, int e) {
    int i = blockIdx.x * blockDim.x + threadIdx.x;
    if (i < e) atomicAdd(&g_deg[dst[i]], 1);
}

__global__ void k_scan1(int n) {
    __shared__ int sm[1024];
    int i = blockIdx.x * 1024 + threadIdx.x;
    int v = (i < n) ? g_deg[i] : 0;
    sm[threadIdx.x] = v;
    __syncthreads();
    for (int off = 1; off < 1024; off <<= 1) {
        int t = (threadIdx.x >= off) ? sm[threadIdx.x - off] : 0;
        __syncthreads();
        sm[threadIdx.x] += t;
        __syncthreads();
    }
    if (i < n) g_rowoff[i] = sm[threadIdx.x] - v;
    if (threadIdx.x == 1023) g_bsum[blockIdx.x] = sm[1023];
}

__global__ void k_scan2(int nb) {
    if (threadIdx.x == 0 && blockIdx.x == 0) {
        int s = 0;
        for (int b = 0; b < nb; b++) { int t = g_bsum[b]; g_bsum[b] = s; s += t; }
    }
}

__global__ void k_scan3(int n, int e) {
    int i = blockIdx.x * 1024 + threadIdx.x;
    if (i < n) {
        int r = g_rowoff[i] + g_bsum[i >> 10];
        g_rowoff[i] = r;
        g_cursor[i] = r;
    }
    if (i == 0) g_rowoff[n] = e;
}

__global__ void k_scatter(const int* __restrict__ dst, int e) {
    int i = blockIdx.x * blockDim.x + threadIdx.x;
    if (i < e) {
        int p = atomicAdd(&g_cursor[dst[i]], 1);
        g_eids[p] = i;
    }
}

// ---------------- fused softmax + aggregate (warp per node, zero atomics) ------
__global__ __launch_bounds__(256)
void k_agg(const int* __restrict__ src, const float* __restrict__ bias,
           float* __restrict__ out_h, float* __restrict__ out_attn, int n) {
    int warp = (blockIdx.x * blockDim.x + threadIdx.x) >> 5;
    int lane = threadIdx.x & 31;
    if (warp >= n) return;
    const int beg = g_rowoff[warp], end = g_rowoff[warp + 1];

    // er for this node (broadcast load, identical on all lanes)
    float4 er0 = *(const float4*)(g_er + (size_t)warp * 8);
    float4 er1 = *(const float4*)(g_er + (size_t)warp * 8 + 4);
    const float er[8] = {er0.x, er0.y, er0.z, er0.w, er1.x, er1.y, er1.z, er1.w};

    // ---- pass 1: per-head max over edges (lanes parallel) ----
    float m[8];
#pragma unroll
    for (int h = 0; h < 8; h++) m[h] = -1e30f;
    for (int p = beg + lane; p < end; p += 32) {
        int e = g_eids[p];
        int s = src[e];
        float4 l0 = *(const float4*)(g_el + (size_t)s * 8);
        float4 l1 = *(const float4*)(g_el + (size_t)s * 8 + 4);
        float lv[8] = {l0.x, l0.y, l0.z, l0.w, l1.x, l1.y, l1.z, l1.w};
#pragma unroll
        for (int h = 0; h < 8; h++) {
            float v = lv[h] + er[h];
            v = v > 0.f ? v : 0.2f * v;
            m[h] = fmaxf(m[h], v);
        }
    }
#pragma unroll
    for (int off = 16; off; off >>= 1)
#pragma unroll
        for (int h = 0; h < 8; h++)
            m[h] = fmaxf(m[h], __shfl_xor_sync(0xffffffffu, m[h], off));

    // ---- pass 2: serial edges; unnormalized w -> attn; sum + weighted gather ----
    float s_[8], acc[8];
#pragma unroll
    for (int h = 0; h < 8; h++) { s_[h] = 0.f; acc[h] = 0.f; }

    for (int base = beg; base < end; base += 32) {
        int p = base + lane;
        int e = 0, sr = 0;
        if (p < end) { e = g_eids[p]; sr = src[e]; }
        int cnt = min(32, end - base);
        for (int j = 0; j < cnt; j++) {
            int ej = __shfl_sync(0xffffffffu, e, j);
            int sj = __shfl_sync(0xffffffffu, sr, j);
            float4 l0 = *(const float4*)(g_el + (size_t)sj * 8);
            float4 l1 = *(const float4*)(g_el + (size_t)sj * 8 + 4);
            float lv[8] = {l0.x, l0.y, l0.z, l0.w, l1.x, l1.y, l1.z, l1.w};
            float w[8];
#pragma unroll
            for (int h = 0; h < 8; h++) {
                float v = lv[h] + er[h];
                v = v > 0.f ? v : 0.2f * v;
                w[h] = __expf(v - m[h]);
                s_[h] += w[h];
            }
            if (lane == 0) {
                *(float4*)(out_attn + (size_t)ej * 8)     = make_float4(w[0], w[1], w[2], w[3]);
                *(float4*)(out_attn + (size_t)ej * 8 + 4) = make_float4(w[4], w[5], w[6], w[7]);
            }
            const float* fp = g_ft + (size_t)sj * HD + lane;
#pragma unroll
            for (int h = 0; h < 8; h++)
                acc[h] += w[h] * fp[h * 32];
        }
    }

    float inv[8];
#pragma unroll
    for (int h = 0; h < 8; h++) inv[h] = (s_[h] > 0.f) ? 1.f / s_[h] : 0.f;

    __syncwarp();
    // ---- pass 3: normalize attn in place (lanes parallel) ----
    for (int p = beg + lane; p < end; p += 32) {
        int e = g_eids[p];
        float4 a0 = *(const float4*)(out_attn + (size_t)e * 8);
        float4 a1 = *(const float4*)(out_attn + (size_t)e * 8 + 4);
        a0.x *= inv[0]; a0.y *= inv[1]; a0.z *= inv[2]; a0.w *= inv[3];
        a1.x *= inv[4]; a1.y *= inv[5]; a1.z *= inv[6]; a1.w *= inv[7];
        *(float4*)(out_attn + (size_t)e * 8)     = a0;
        *(float4*)(out_attn + (size_t)e * 8 + 4) = a1;
    }

    // ---- output h: mean over heads of (normalized sum + bias) ----
    float msum = 0.f;
#pragma unroll
    for (int h = 0; h < 8; h++)
        msum += acc[h] * inv[h] + bias[h * 32 + lane];
    out_h[(size_t)warp * 32 + lane] = msum * 0.125f;
}

// ---------------- launch --------------------------------------------------------
extern "C" void kernel_launch(void* const* d_in, const int* in_sizes, int n_in,
                              void* d_out, int out_size) {
    const float* feat = (const float*)d_in[0];
    const int*   src  = (const int*)d_in[1];
    const int*   dst  = (const int*)d_in[2];
    const float* W    = (const float*)d_in[3];
    const float* al   = (const float*)d_in[4];
    const float* ar   = (const float*)d_in[5];
    const float* bias = (const float*)d_in[6];

    int n = in_sizes[0] / INF_;
    int e = in_sizes[1];

    float* out      = (float*)d_out;
    float* out_h    = out;                   // [n, 32]
    float* out_attn = out + (size_t)n * 32;  // [e, 8]

    const int SMEM = (32768 + 128 * 129) * 4;
    cudaFuncSetAttribute(k_gemm, cudaFuncAttributeMaxDynamicSharedMemorySize, SMEM);

    k_init<<<(n + 255) / 256, 256>>>(n);
    k_gemm<<<(n + 127) / 128, 512, SMEM>>>(feat, W, al, ar, n);

    int nb = (n + 1023) / 1024;
    k_hist<<<(e + 255) / 256, 256>>>(dst, e);
    k_scan1<<<nb, 1024>>>(n);
    k_scan2<<<1, 32>>>(nb);
    k_scan3<<<nb, 1024>>>(n, e);
    k_scatter<<<(e + 255) / 256, 256>>>(dst, e);

    k_agg<<<(n + 7) / 8, 256>>>(src, bias, out_h, out_attn, n);
}